// round 2
// baseline (speedup 1.0000x reference)
#include <cuda_runtime.h>
#include <cuda_bf16.h>
#include <cstdint>
#include <cstddef>

#define NN 4096
#define DM 256
#define NH 8
#define DH 32

// ---------------- scratch (device globals; no allocation) ----------------
__device__ __nv_bfloat16 g_P_hi[(size_t)NH * NN * NN];   // relu(QK^T) hi split, [h][n][m]
__device__ __nv_bfloat16 g_P_lo[(size_t)NH * NN * NN];   // lo split
__device__ __nv_bfloat16 g_RT_hi[(size_t)NN * NN];       // rescale(dist)^T hi, [p][m]
__device__ __nv_bfloat16 g_RT_lo[(size_t)NN * NN];       // lo split
__device__ float         g_S[(size_t)NH * NN * NN];      // scores -> attn (in place)
__device__ float         g_Q[(size_t)NN * DM];
__device__ float         g_K[(size_t)NN * DM];
__device__ float         g_Vp[(size_t)NN * DM];

// ---------------- helpers ----------------
__device__ __forceinline__ uint32_t smem_u32(const void* p) {
    uint32_t a;
    asm("{ .reg .u64 t; cvta.to.shared.u64 t, %1; cvt.u32.u64 %0, t; }" : "=r"(a) : "l"(p));
    return a;
}

__device__ __forceinline__ void ldsm_x4(uint32_t* r, uint32_t addr) {
    asm volatile("ldmatrix.sync.aligned.m8n8.x4.shared.b16 {%0,%1,%2,%3}, [%4];"
                 : "=r"(r[0]), "=r"(r[1]), "=r"(r[2]), "=r"(r[3]) : "r"(addr));
}

__device__ __forceinline__ void mma16816(float* c, const uint32_t* a, const uint32_t* b) {
    asm volatile(
        "mma.sync.aligned.m16n8k16.row.col.f32.bf16.bf16.f32 "
        "{%0,%1,%2,%3}, {%4,%5,%6,%7}, {%8,%9}, {%0,%1,%2,%3};"
        : "+f"(c[0]), "+f"(c[1]), "+f"(c[2]), "+f"(c[3])
        : "r"(a[0]), "r"(a[1]), "r"(a[2]), "r"(a[3]), "r"(b[0]), "r"(b[1]));
}

__device__ __forceinline__ void cp16(uint32_t smem, const void* gmem) {
    asm volatile("cp.async.cg.shared.global [%0], [%1], 16;" :: "r"(smem), "l"(gmem));
}

// ---------------- kernel 1: R^T = rescale(dist)^T, bf16 split ----------------
__global__ void __launch_bounds__(1024) k_rescale(const float* __restrict__ dist) {
    __shared__ float t[32][33];
    const int m0 = blockIdx.y * 32, p0 = blockIdx.x * 32;
    const int tx = threadIdx.x, ty = threadIdx.y;
    float d = dist[(size_t)(m0 + ty) * NN + p0 + tx];
    t[ty][tx] = 3.718281828459045f / (1.0f + expf(1.0f - d));
    __syncthreads();
    float r = t[tx][ty];  // = R[m0+tx][p0+ty]
    __nv_bfloat16 hi = __float2bfloat16(r);
    float lo = r - __bfloat162float(hi);
    size_t o = (size_t)(p0 + ty) * NN + m0 + tx;
    g_RT_hi[o] = hi;
    g_RT_lo[o] = __float2bfloat16(lo);
}

// ---------------- kernel 2: projections out[n][j] = sum_k X[n][k]*W[j][k] ----------------
__global__ void __launch_bounds__(1024) k_proj(const float* __restrict__ X,
                                               const float* __restrict__ W, int which) {
    float* out = (which == 0) ? g_Q : ((which == 1) ? g_K : g_Vp);
    __shared__ float Xs[32][33], Ws[32][33];
    const int n0 = blockIdx.y * 32, j0 = blockIdx.x * 32;
    const int tx = threadIdx.x, ty = threadIdx.y;
    float acc = 0.f;
    for (int k0 = 0; k0 < DM; k0 += 32) {
        Xs[ty][tx] = X[(size_t)(n0 + ty) * DM + k0 + tx];
        Ws[ty][tx] = W[(size_t)(j0 + ty) * DM + k0 + tx];
        __syncthreads();
#pragma unroll
        for (int kk = 0; kk < 32; kk++) acc += Xs[ty][kk] * Ws[tx][kk];
        __syncthreads();
    }
    out[(size_t)(n0 + ty) * DM + j0 + tx] = acc;
}

// ---------------- kernel 3: P[h][n][m] = relu(Q_h[n]·K_h[m]), bf16 split ----------------
__global__ void __launch_bounds__(1024) k_qk() {
    __shared__ float Qs[32][33], Ks[32][33];
    const int h = blockIdx.z;
    const int n0 = blockIdx.y * 32, m0 = blockIdx.x * 32;
    const int tx = threadIdx.x, ty = threadIdx.y;
    Qs[ty][tx] = g_Q[(size_t)(n0 + ty) * DM + h * DH + tx];
    Ks[ty][tx] = g_K[(size_t)(m0 + ty) * DM + h * DH + tx];
    __syncthreads();
    float acc = 0.f;
#pragma unroll
    for (int d = 0; d < 32; d++) acc += Qs[ty][d] * Ks[tx][d];
    acc = fmaxf(acc, 0.f);
    __nv_bfloat16 hi = __float2bfloat16(acc);
    float lo = acc - __bfloat162float(hi);
    size_t o = ((size_t)h * NN + n0 + ty) * NN + m0 + tx;
    g_P_hi[o] = hi;
    g_P_lo[o] = __float2bfloat16(lo);
}

// ---------------- kernel 4: big GEMM (HMMA mma.sync, split precision) ----------------
// S[h][m][n] = (sum_k Phi[m,k]*Rhi[n,k] + Phi*Rlo + Plo*Rhi) / sqrt(32)
// CTA tile 128x128, K-chunk 32, 2-stage cp.async.
// smem per array: 128 rows * 80 bytes (32 bf16 + 16B pad) = 10240 B.
#define ROWB 80
#define ARR_SZ (128 * ROWB)
#define STAGE_SZ (4 * ARR_SZ)          // Ahi, Alo, Bhi, Blo
#define GEMM_SMEM (2 * STAGE_SZ)       // 81920 B

__global__ void __launch_bounds__(256) k_gemm() {
    extern __shared__ char smem[];
    const uint32_t sb = smem_u32(smem);
    const int tid = threadIdx.x;
    const int wid = tid >> 5, lane = tid & 31;
    const int h = blockIdx.z;
    const int m0 = blockIdx.y * 128, n0 = blockIdx.x * 128;

    const __nv_bfloat16* __restrict__ Ahi = g_P_hi + ((size_t)h * NN + m0) * NN;
    const __nv_bfloat16* __restrict__ Alo = g_P_lo + ((size_t)h * NN + m0) * NN;
    const __nv_bfloat16* __restrict__ Bhi = g_RT_hi + (size_t)n0 * NN;
    const __nv_bfloat16* __restrict__ Blo = g_RT_lo + (size_t)n0 * NN;

    // loader mapping: per array, chunk = 16B; row = cid>>2, c = cid&3; 512 chunks, 256 thr x2
    const int r0l = tid >> 2, c0l = tid & 3;

    auto issue_stage = [&](int kc, int stage) {
        const uint32_t s0 = sb + stage * STAGE_SZ;
#pragma unroll
        for (int j = 0; j < 2; j++) {
            const int row = r0l + j * 64;
            const uint32_t so = (uint32_t)(row * ROWB + c0l * 16);
            const size_t go = (size_t)row * NN + kc + c0l * 8;
            cp16(s0 + 0 * ARR_SZ + so, Ahi + go);
            cp16(s0 + 1 * ARR_SZ + so, Alo + go);
            cp16(s0 + 2 * ARR_SZ + so, Bhi + go);
            cp16(s0 + 3 * ARR_SZ + so, Blo + go);
        }
        asm volatile("cp.async.commit_group;" ::: "memory");
    };

    // warp layout: 4 (M) x 2 (N); warp tile 32 (M) x 64 (N)
    const int wm = wid & 3, wn = wid >> 2;
    float acc[2][8][4];
#pragma unroll
    for (int mi = 0; mi < 2; mi++)
#pragma unroll
        for (int ni = 0; ni < 8; ni++)
#pragma unroll
            for (int q = 0; q < 4; q++) acc[mi][ni][q] = 0.f;

    // ldmatrix per-thread source rows/cols (within tile, before k offset)
    const int sel = lane >> 3, l7 = lane & 7;
    // A: sel0:(r+0,k0) sel1:(r+8,k0) sel2:(r+0,k8) sel3:(r+8,k8)
    const int a_row = wm * 32 + (sel & 1) * 8 + l7;
    const int a_colb = (sel >> 1) * 16;
    // B: sel0:(n+0,k0) sel1:(n+0,k8) sel2:(n+8,k0) sel3:(n+8,k8)
    const int b_row_base = wn * 64 + (sel >> 1) * 8 + l7;
    const int b_colb = (sel & 1) * 16;

    issue_stage(0, 0);

    for (int it = 0; it < NN / 32; it++) {
        __syncthreads();   // everyone done reading the buffer we are about to overwrite
        if (it + 1 < NN / 32) {
            issue_stage((it + 1) * 32, (it + 1) & 1);
            asm volatile("cp.async.wait_group 1;" ::: "memory");
        } else {
            asm volatile("cp.async.wait_group 0;" ::: "memory");
        }
        __syncthreads();

        const uint32_t s0 = sb + (it & 1) * STAGE_SZ;
        const uint32_t pAhi = s0 + 0 * ARR_SZ, pAlo = s0 + 1 * ARR_SZ;
        const uint32_t pBhi = s0 + 2 * ARR_SZ, pBlo = s0 + 3 * ARR_SZ;

#pragma unroll
        for (int ks = 0; ks < 2; ks++) {   // two k16 steps within the 32-chunk
            const int kb = ks * 32;        // byte offset of k16 step
            uint32_t ahi[2][4], alo[2][4];
#pragma unroll
            for (int mi = 0; mi < 2; mi++) {
                const uint32_t ao = (uint32_t)((a_row + mi * 16) * ROWB + kb + a_colb);
                ldsm_x4(ahi[mi], pAhi + ao);
                ldsm_x4(alo[mi], pAlo + ao);
            }
            uint32_t bhi[8][2], blo[8][2];
#pragma unroll
            for (int nb = 0; nb < 4; nb++) {   // 4 x (n16 k16)
                const uint32_t bo = (uint32_t)((b_row_base + nb * 16) * ROWB + kb + b_colb);
                uint32_t t[4];
                ldsm_x4(t, pBhi + bo);
                bhi[2 * nb][0] = t[0]; bhi[2 * nb][1] = t[1];
                bhi[2 * nb + 1][0] = t[2]; bhi[2 * nb + 1][1] = t[3];
                ldsm_x4(t, pBlo + bo);
                blo[2 * nb][0] = t[0]; blo[2 * nb][1] = t[1];
                blo[2 * nb + 1][0] = t[2]; blo[2 * nb + 1][1] = t[3];
            }
#pragma unroll
            for (int mi = 0; mi < 2; mi++)
#pragma unroll
                for (int ni = 0; ni < 8; ni++) {
                    mma16816(acc[mi][ni], ahi[mi], bhi[ni]);
                    mma16816(acc[mi][ni], ahi[mi], blo[ni]);
                    mma16816(acc[mi][ni], alo[mi], bhi[ni]);
                }
        }
    }

    // epilogue
    const float inv_s = 0.17677669529663687f;  // 1/sqrt(32)
    const int er = lane >> 2, ec = (lane & 3) * 2;
#pragma unroll
    for (int mi = 0; mi < 2; mi++) {
#pragma unroll
        for (int ni = 0; ni < 8; ni++) {
            const int col = n0 + wn * 64 + ni * 8 + ec;
            const int row = m0 + wm * 32 + mi * 16 + er;
            float2 v0 = make_float2(acc[mi][ni][0] * inv_s, acc[mi][ni][1] * inv_s);
            float2 v1 = make_float2(acc[mi][ni][2] * inv_s, acc[mi][ni][3] * inv_s);
            *(float2*)(g_S + ((size_t)h * NN + row) * NN + col) = v0;
            *(float2*)(g_S + ((size_t)h * NN + row + 8) * NN + col) = v1;
        }
    }
}

// ---------------- kernel 5: softmax row-wise in place ----------------
__global__ void __launch_bounds__(256) k_softmax() {
    const size_t row = blockIdx.x;
    float* p = g_S + row * (size_t)NN;
    const int tid = threadIdx.x;
    float x[16];
    float mx = -1e30f;
#pragma unroll
    for (int i = 0; i < 16; i++) { x[i] = p[tid + (i << 8)]; mx = fmaxf(mx, x[i]); }
    __shared__ float red[8];
#pragma unroll
    for (int o = 16; o; o >>= 1) mx = fmaxf(mx, __shfl_xor_sync(0xffffffffu, mx, o));
    if ((tid & 31) == 0) red[tid >> 5] = mx;
    __syncthreads();
    mx = red[0];
#pragma unroll
    for (int i = 1; i < 8; i++) mx = fmaxf(mx, red[i]);
    float s = 0.f;
#pragma unroll
    for (int i = 0; i < 16; i++) { x[i] = __expf(x[i] - mx); s += x[i]; }
#pragma unroll
    for (int o = 16; o; o >>= 1) s += __shfl_xor_sync(0xffffffffu, s, o);
    __syncthreads();
    if ((tid & 31) == 0) red[tid >> 5] = s;
    __syncthreads();
    s = ((red[0] + red[1]) + (red[2] + red[3])) + ((red[4] + red[5]) + (red[6] + red[7]));
    const float inv = 1.0f / s;
#pragma unroll
    for (int i = 0; i < 16; i++) p[tid + (i << 8)] = x[i] * inv;
}

// ---------------- kernel 6: out[n][h*32+d] = sum_p attn[h][n][p] * V[p][h*32+d] ----------------
__global__ void __launch_bounds__(256) k_av(float* __restrict__ out) {
    const int h = blockIdx.y;
    const int n = blockIdx.x;
    const int tx = threadIdx.x;  // d: 0..31
    const int ty = threadIdx.y;  // p split: 0..7
    const float* __restrict__ arow = g_S + ((size_t)h * NN + n) * NN;
    const float* __restrict__ vptr = g_Vp + h * DH + tx;
    float a0 = 0.f, a1 = 0.f, a2 = 0.f, a3 = 0.f;
    for (int p = ty; p < NN; p += 32) {
        a0 += arow[p]      * vptr[(size_t)(p)      * DM];
        a1 += arow[p + 8]  * vptr[(size_t)(p + 8)  * DM];
        a2 += arow[p + 16] * vptr[(size_t)(p + 16) * DM];
        a3 += arow[p + 24] * vptr[(size_t)(p + 24) * DM];
    }
    float acc = (a0 + a1) + (a2 + a3);
    __shared__ float red[8][32];
    red[ty][tx] = acc;
    __syncthreads();
    if (ty == 0) {
        float s = ((red[0][tx] + red[1][tx]) + (red[2][tx] + red[3][tx])) +
                  ((red[4][tx] + red[5][tx]) + (red[6][tx] + red[7][tx]));
        out[(size_t)n * DM + h * DH + tx] = s;
    }
}

// ---------------- launch ----------------
extern "C" void kernel_launch(void* const* d_in, const int* in_sizes, int n_in,
                              void* d_out, int out_size) {
    (void)in_sizes; (void)n_in; (void)out_size;
    const float* Qin  = (const float*)d_in[0];
    const float* Kin  = (const float*)d_in[1];
    const float* Vin  = (const float*)d_in[2];
    // d_in[3] = adj_matrix: dead code in the reference
    const float* dist = (const float*)d_in[4];
    const float* WQ   = (const float*)d_in[5];
    const float* WK   = (const float*)d_in[6];
    const float* WV   = (const float*)d_in[7];
    float* out = (float*)d_out;

    k_rescale<<<dim3(128, 128), dim3(32, 32)>>>(dist);
    k_proj<<<dim3(8, 128), dim3(32, 32)>>>(Qin, WQ, 0);
    k_proj<<<dim3(8, 128), dim3(32, 32)>>>(Kin, WK, 1);
    k_proj<<<dim3(8, 128), dim3(32, 32)>>>(Vin, WV, 2);
    k_qk<<<dim3(128, 128, 8), dim3(32, 32)>>>();

    cudaFuncSetAttribute(k_gemm, cudaFuncAttributeMaxDynamicSharedMemorySize, GEMM_SMEM);
    k_gemm<<<dim3(32, 32, 8), 256, GEMM_SMEM>>>();

    k_softmax<<<dim3(NH * NN), 256>>>();
    k_av<<<dim3(NN, NH), dim3(32, 8)>>>(out);
}

// round 3
// speedup vs baseline: 1.0247x; 1.0247x over previous
#include <cuda_runtime.h>
#include <cuda_fp16.h>
#include <cstdint>
#include <cstddef>

#define NN 4096
#define DM 256
#define NH 8
#define DH 32

// ---------------- scratch (device globals; no allocation) ----------------
__device__ __half g_P_hi[(size_t)NH * NN * NN];   // relu(QK^T) hi split, [h][n][m]
__device__ __half g_P_lo[(size_t)NH * NN * NN];   // lo split
__device__ __half g_RT_hi[(size_t)NN * NN];       // rescale(dist)^T hi, [p][m]
__device__ __half g_RT_lo[(size_t)NN * NN];       // lo split
__device__ float  g_S[(size_t)NH * NN * NN];      // scores -> attn (in place)
__device__ float  g_Q[(size_t)NN * DM];
__device__ float  g_K[(size_t)NN * DM];
__device__ float  g_Vp[(size_t)NN * DM];

// ---------------- helpers ----------------
__device__ __forceinline__ uint32_t smem_u32(const void* p) {
    uint32_t a;
    asm("{ .reg .u64 t; cvta.to.shared.u64 t, %1; cvt.u32.u64 %0, t; }" : "=r"(a) : "l"(p));
    return a;
}

__device__ __forceinline__ void ldsm_x4(uint32_t* r, uint32_t addr) {
    asm volatile("ldmatrix.sync.aligned.m8n8.x4.shared.b16 {%0,%1,%2,%3}, [%4];"
                 : "=r"(r[0]), "=r"(r[1]), "=r"(r[2]), "=r"(r[3]) : "r"(addr));
}

__device__ __forceinline__ void mma16816(float* c, const uint32_t* a, const uint32_t* b) {
    asm volatile(
        "mma.sync.aligned.m16n8k16.row.col.f32.f16.f16.f32 "
        "{%0,%1,%2,%3}, {%4,%5,%6,%7}, {%8,%9}, {%0,%1,%2,%3};"
        : "+f"(c[0]), "+f"(c[1]), "+f"(c[2]), "+f"(c[3])
        : "r"(a[0]), "r"(a[1]), "r"(a[2]), "r"(a[3]), "r"(b[0]), "r"(b[1]));
}

__device__ __forceinline__ void cp16(uint32_t smem, const void* gmem) {
    asm volatile("cp.async.cg.shared.global [%0], [%1], 16;" :: "r"(smem), "l"(gmem));
}

// ---------------- kernel 1: R^T = rescale(dist)^T, fp16 split ----------------
__global__ void __launch_bounds__(1024) k_rescale(const float* __restrict__ dist) {
    __shared__ float t[32][33];
    const int m0 = blockIdx.y * 32, p0 = blockIdx.x * 32;
    const int tx = threadIdx.x, ty = threadIdx.y;
    float d = dist[(size_t)(m0 + ty) * NN + p0 + tx];
    t[ty][tx] = 3.718281828459045f / (1.0f + expf(1.0f - d));
    __syncthreads();
    float r = t[tx][ty];  // = R[m0+tx][p0+ty]
    __half hi = __float2half(r);
    float lo = r - __half2float(hi);
    size_t o = (size_t)(p0 + ty) * NN + m0 + tx;
    g_RT_hi[o] = hi;
    g_RT_lo[o] = __float2half(lo);
}

// ---------------- kernel 2: projections out[n][j] = sum_k X[n][k]*W[j][k] ----------------
__global__ void __launch_bounds__(1024) k_proj(const float* __restrict__ X,
                                               const float* __restrict__ W, int which) {
    float* out = (which == 0) ? g_Q : ((which == 1) ? g_K : g_Vp);
    __shared__ float Xs[32][33], Ws[32][33];
    const int n0 = blockIdx.y * 32, j0 = blockIdx.x * 32;
    const int tx = threadIdx.x, ty = threadIdx.y;
    float acc = 0.f;
    for (int k0 = 0; k0 < DM; k0 += 32) {
        Xs[ty][tx] = X[(size_t)(n0 + ty) * DM + k0 + tx];
        Ws[ty][tx] = W[(size_t)(j0 + ty) * DM + k0 + tx];
        __syncthreads();
#pragma unroll
        for (int kk = 0; kk < 32; kk++) acc += Xs[ty][kk] * Ws[tx][kk];
        __syncthreads();
    }
    out[(size_t)(n0 + ty) * DM + j0 + tx] = acc;
}

// ---------------- kernel 3: P[h][n][m] = relu(Q_h[n]·K_h[m]), fp16 split ----------------
__global__ void __launch_bounds__(1024) k_qk() {
    __shared__ float Qs[32][33], Ks[32][33];
    const int h = blockIdx.z;
    const int n0 = blockIdx.y * 32, m0 = blockIdx.x * 32;
    const int tx = threadIdx.x, ty = threadIdx.y;
    Qs[ty][tx] = g_Q[(size_t)(n0 + ty) * DM + h * DH + tx];
    Ks[ty][tx] = g_K[(size_t)(m0 + ty) * DM + h * DH + tx];
    __syncthreads();
    float acc = 0.f;
#pragma unroll
    for (int d = 0; d < 32; d++) acc += Qs[ty][d] * Ks[tx][d];
    acc = fmaxf(acc, 0.f);
    __half hi = __float2half(acc);
    float lo = acc - __half2float(hi);
    size_t o = ((size_t)h * NN + n0 + ty) * NN + m0 + tx;
    g_P_hi[o] = hi;
    g_P_lo[o] = __float2half(lo);
}

// ---------------- kernel 4: big GEMM (HMMA mma.sync, split precision) ----------------
// S[h][m][n] = (Phi·Rhi + Phi·Rlo + Plo·Rhi) / sqrt(32)
// CTA tile 128x128, K-chunk 32, 3-stage cp.async, one barrier per chunk.
#define ROWB 80
#define ARR_SZ (128 * ROWB)
#define STAGE_SZ (4 * ARR_SZ)            // Ahi, Alo, Bhi, Blo = 40960 B
#define STAGES 3
#define GEMM_SMEM (STAGES * STAGE_SZ)    // 122880 B
#define KITERS (NN / 32)                 // 128

__global__ void __launch_bounds__(256) k_gemm() {
    extern __shared__ char smem[];
    const uint32_t sb = smem_u32(smem);
    const int tid = threadIdx.x;
    const int wid = tid >> 5, lane = tid & 31;
    const int h = blockIdx.z;
    const int m0 = blockIdx.y * 128, n0 = blockIdx.x * 128;

    const __half* __restrict__ Ahi = g_P_hi + ((size_t)h * NN + m0) * NN;
    const __half* __restrict__ Alo = g_P_lo + ((size_t)h * NN + m0) * NN;
    const __half* __restrict__ Bhi = g_RT_hi + (size_t)n0 * NN;
    const __half* __restrict__ Blo = g_RT_lo + (size_t)n0 * NN;

    const int r0l = tid >> 2, c0l = tid & 3;

    auto issue_stage = [&](int it) {
        if (it < KITERS) {
            const uint32_t s0 = sb + (it % STAGES) * STAGE_SZ;
            const int kc = it * 32;
#pragma unroll
            for (int j = 0; j < 2; j++) {
                const int row = r0l + j * 64;
                const uint32_t so = (uint32_t)(row * ROWB + c0l * 16);
                const size_t go = (size_t)row * NN + kc + c0l * 8;
                cp16(s0 + 0 * ARR_SZ + so, Ahi + go);
                cp16(s0 + 1 * ARR_SZ + so, Alo + go);
                cp16(s0 + 2 * ARR_SZ + so, Bhi + go);
                cp16(s0 + 3 * ARR_SZ + so, Blo + go);
            }
        }
        asm volatile("cp.async.commit_group;" ::: "memory");
    };

    // warp layout: 4 (M) x 2 (N); warp tile 32 (M) x 64 (N)
    const int wm = wid & 3, wn = wid >> 2;
    float acc[2][8][4];
#pragma unroll
    for (int mi = 0; mi < 2; mi++)
#pragma unroll
        for (int ni = 0; ni < 8; ni++)
#pragma unroll
            for (int q = 0; q < 4; q++) acc[mi][ni][q] = 0.f;

    const int sel = lane >> 3, l7 = lane & 7;
    const int a_row = wm * 32 + (sel & 1) * 8 + l7;
    const int a_colb = (sel >> 1) * 16;
    const int b_row_base = wn * 64 + (sel >> 1) * 8 + l7;
    const int b_colb = (sel & 1) * 16;

    issue_stage(0);
    issue_stage(1);

    for (int it = 0; it < KITERS; it++) {
        asm volatile("cp.async.wait_group %0;" :: "n"(STAGES - 2) : "memory");
        __syncthreads();
        issue_stage(it + STAGES - 1);

        const uint32_t s0 = sb + (it % STAGES) * STAGE_SZ;
        const uint32_t pAhi = s0 + 0 * ARR_SZ, pAlo = s0 + 1 * ARR_SZ;
        const uint32_t pBhi = s0 + 2 * ARR_SZ, pBlo = s0 + 3 * ARR_SZ;

#pragma unroll
        for (int ks = 0; ks < 2; ks++) {   // two k16 steps within the 32-chunk
            const int kb = ks * 32;        // byte offset of k16 step
            uint32_t ahi[2][4], alo[2][4];
#pragma unroll
            for (int mi = 0; mi < 2; mi++) {
                const uint32_t ao = (uint32_t)((a_row + mi * 16) * ROWB + kb + a_colb);
                ldsm_x4(ahi[mi], pAhi + ao);
                ldsm_x4(alo[mi], pAlo + ao);
            }
            uint32_t bhi[8][2], blo[8][2];
#pragma unroll
            for (int nb = 0; nb < 4; nb++) {
                const uint32_t bo = (uint32_t)((b_row_base + nb * 16) * ROWB + kb + b_colb);
                uint32_t t[4];
                ldsm_x4(t, pBhi + bo);
                bhi[2 * nb][0] = t[0]; bhi[2 * nb][1] = t[1];
                bhi[2 * nb + 1][0] = t[2]; bhi[2 * nb + 1][1] = t[3];
                ldsm_x4(t, pBlo + bo);
                blo[2 * nb][0] = t[0]; blo[2 * nb][1] = t[1];
                blo[2 * nb + 1][0] = t[2]; blo[2 * nb + 1][1] = t[3];
            }
            // 3 sweeps: within each sweep all 16 MMAs hit distinct accumulators
#pragma unroll
            for (int mi = 0; mi < 2; mi++)
#pragma unroll
                for (int ni = 0; ni < 8; ni++) mma16816(acc[mi][ni], ahi[mi], bhi[ni]);
#pragma unroll
            for (int mi = 0; mi < 2; mi++)
#pragma unroll
                for (int ni = 0; ni < 8; ni++) mma16816(acc[mi][ni], ahi[mi], blo[ni]);
#pragma unroll
            for (int mi = 0; mi < 2; mi++)
#pragma unroll
                for (int ni = 0; ni < 8; ni++) mma16816(acc[mi][ni], alo[mi], bhi[ni]);
        }
    }

    // epilogue
    const float inv_s = 0.17677669529663687f;  // 1/sqrt(32)
    const int er = lane >> 2, ec = (lane & 3) * 2;
#pragma unroll
    for (int mi = 0; mi < 2; mi++) {
#pragma unroll
        for (int ni = 0; ni < 8; ni++) {
            const int col = n0 + wn * 64 + ni * 8 + ec;
            const int row = m0 + wm * 32 + mi * 16 + er;
            float2 v0 = make_float2(acc[mi][ni][0] * inv_s, acc[mi][ni][1] * inv_s);
            float2 v1 = make_float2(acc[mi][ni][2] * inv_s, acc[mi][ni][3] * inv_s);
            *(float2*)(g_S + ((size_t)h * NN + row) * NN + col) = v0;
            *(float2*)(g_S + ((size_t)h * NN + row + 8) * NN + col) = v1;
        }
    }
}

// ---------------- kernel 5: softmax row-wise in place ----------------
__global__ void __launch_bounds__(256) k_softmax() {
    const size_t row = blockIdx.x;
    float* p = g_S + row * (size_t)NN;
    const int tid = threadIdx.x;
    float x[16];
    float mx = -1e30f;
#pragma unroll
    for (int i = 0; i < 16; i++) { x[i] = p[tid + (i << 8)]; mx = fmaxf(mx, x[i]); }
    __shared__ float red[8];
#pragma unroll
    for (int o = 16; o; o >>= 1) mx = fmaxf(mx, __shfl_xor_sync(0xffffffffu, mx, o));
    if ((tid & 31) == 0) red[tid >> 5] = mx;
    __syncthreads();
    mx = red[0];
#pragma unroll
    for (int i = 1; i < 8; i++) mx = fmaxf(mx, red[i]);
    float s = 0.f;
#pragma unroll
    for (int i = 0; i < 16; i++) { x[i] = __expf(x[i] - mx); s += x[i]; }
#pragma unroll
    for (int o = 16; o; o >>= 1) s += __shfl_xor_sync(0xffffffffu, s, o);
    __syncthreads();
    if ((tid & 31) == 0) red[tid >> 5] = s;
    __syncthreads();
    s = ((red[0] + red[1]) + (red[2] + red[3])) + ((red[4] + red[5]) + (red[6] + red[7]));
    const float inv = 1.0f / s;
#pragma unroll
    for (int i = 0; i < 16; i++) p[tid + (i << 8)] = x[i] * inv;
}

// ---------------- kernel 6: out[n][h*32+d] = sum_p attn[h][n][p] * V[p][h*32+d] ----------------
__global__ void __launch_bounds__(256) k_av(float* __restrict__ out) {
    const int h = blockIdx.y;
    const int n = blockIdx.x;
    const int tx = threadIdx.x;  // d: 0..31
    const int ty = threadIdx.y;  // p split: 0..7
    const float* __restrict__ arow = g_S + ((size_t)h * NN + n) * NN;
    const float* __restrict__ vptr = g_Vp + h * DH + tx;
    float a0 = 0.f, a1 = 0.f, a2 = 0.f, a3 = 0.f;
    for (int p = ty; p < NN; p += 32) {
        a0 += arow[p]      * vptr[(size_t)(p)      * DM];
        a1 += arow[p + 8]  * vptr[(size_t)(p + 8)  * DM];
        a2 += arow[p + 16] * vptr[(size_t)(p + 16) * DM];
        a3 += arow[p + 24] * vptr[(size_t)(p + 24) * DM];
    }
    float acc = (a0 + a1) + (a2 + a3);
    __shared__ float red[8][32];
    red[ty][tx] = acc;
    __syncthreads();
    if (ty == 0) {
        float s = ((red[0][tx] + red[1][tx]) + (red[2][tx] + red[3][tx])) +
                  ((red[4][tx] + red[5][tx]) + (red[6][tx] + red[7][tx]));
        out[(size_t)n * DM + h * DH + tx] = s;
    }
}

// ---------------- launch ----------------
extern "C" void kernel_launch(void* const* d_in, const int* in_sizes, int n_in,
                              void* d_out, int out_size) {
    (void)in_sizes; (void)n_in; (void)out_size;
    const float* Qin  = (const float*)d_in[0];
    const float* Kin  = (const float*)d_in[1];
    const float* Vin  = (const float*)d_in[2];
    // d_in[3] = adj_matrix: dead code in the reference
    const float* dist = (const float*)d_in[4];
    const float* WQ   = (const float*)d_in[5];
    const float* WK   = (const float*)d_in[6];
    const float* WV   = (const float*)d_in[7];
    float* out = (float*)d_out;

    k_rescale<<<dim3(128, 128), dim3(32, 32)>>>(dist);
    k_proj<<<dim3(8, 128), dim3(32, 32)>>>(Qin, WQ, 0);
    k_proj<<<dim3(8, 128), dim3(32, 32)>>>(Kin, WK, 1);
    k_proj<<<dim3(8, 128), dim3(32, 32)>>>(Vin, WV, 2);
    k_qk<<<dim3(128, 128, 8), dim3(32, 32)>>>();

    cudaFuncSetAttribute(k_gemm, cudaFuncAttributeMaxDynamicSharedMemorySize, GEMM_SMEM);
    k_gemm<<<dim3(32, 32, 8), 256, GEMM_SMEM>>>();

    k_softmax<<<dim3(NH * NN), 256>>>();
    k_av<<<dim3(NN, NH), dim3(32, 8)>>>(out);
}

// round 4
// speedup vs baseline: 1.2462x; 1.2163x over previous
#include <cuda_runtime.h>
#include <cuda_fp16.h>
#include <cstdint>
#include <cstddef>

#define NN 4096
#define DM 256
#define NH 8
#define DH 32

// ---------------- scratch (device globals; no allocation) ----------------
__device__ __half g_P_hi[(size_t)NH * NN * NN];   // relu(QK^T) hi split, [h][n][m]
__device__ __half g_P_lo[(size_t)NH * NN * NN];   // lo split
__device__ __half g_RT_hi[(size_t)NN * NN];       // rescale(dist)^T hi, [p][m]
__device__ __half g_RT_lo[(size_t)NN * NN];       // lo split
__device__ float  g_S[(size_t)NH * NN * NN];      // scores -> attn (in place)
__device__ __half g_Qh[(size_t)NN * DM];          // Q projection fp16 hi/lo
__device__ __half g_Ql[(size_t)NN * DM];
__device__ __half g_Kh[(size_t)NN * DM];
__device__ __half g_Kl[(size_t)NN * DM];
__device__ float  g_Vp[(size_t)NN * DM];

// ---------------- helpers ----------------
__device__ __forceinline__ uint32_t smem_u32(const void* p) {
    uint32_t a;
    asm("{ .reg .u64 t; cvta.to.shared.u64 t, %1; cvt.u32.u64 %0, t; }" : "=r"(a) : "l"(p));
    return a;
}

__device__ __forceinline__ void ldsm_x4(uint32_t* r, uint32_t addr) {
    asm volatile("ldmatrix.sync.aligned.m8n8.x4.shared.b16 {%0,%1,%2,%3}, [%4];"
                 : "=r"(r[0]), "=r"(r[1]), "=r"(r[2]), "=r"(r[3]) : "r"(addr));
}

__device__ __forceinline__ void mma16816(float* c, const uint32_t* a, const uint32_t* b) {
    asm volatile(
        "mma.sync.aligned.m16n8k16.row.col.f32.f16.f16.f32 "
        "{%0,%1,%2,%3}, {%4,%5,%6,%7}, {%8,%9}, {%0,%1,%2,%3};"
        : "+f"(c[0]), "+f"(c[1]), "+f"(c[2]), "+f"(c[3])
        : "r"(a[0]), "r"(a[1]), "r"(a[2]), "r"(a[3]), "r"(b[0]), "r"(b[1]));
}

__device__ __forceinline__ void cp16(uint32_t smem, const void* gmem) {
    asm volatile("cp.async.cg.shared.global [%0], [%1], 16;" :: "r"(smem), "l"(gmem));
}

// ---------------- kernel 1: R^T = rescale(dist)^T, fp16 split ----------------
__global__ void __launch_bounds__(1024) k_rescale(const float* __restrict__ dist) {
    __shared__ float t[32][33];
    const int m0 = blockIdx.y * 32, p0 = blockIdx.x * 32;
    const int tx = threadIdx.x, ty = threadIdx.y;
    float d = dist[(size_t)(m0 + ty) * NN + p0 + tx];
    t[ty][tx] = 3.718281828459045f / (1.0f + expf(1.0f - d));
    __syncthreads();
    float r = t[tx][ty];  // = R[m0+tx][p0+ty]
    __half hi = __float2half(r);
    float lo = r - __half2float(hi);
    size_t o = (size_t)(p0 + ty) * NN + m0 + tx;
    g_RT_hi[o] = hi;
    g_RT_lo[o] = __float2half(lo);
}

// ---------------- kernel 2: projections out[n][j] = sum_k X[n][k]*W[j][k] ----------------
// which: 0 -> Q (fp16 hi/lo), 1 -> K (fp16 hi/lo), 2 -> V (fp32)
__global__ void __launch_bounds__(1024) k_proj(const float* __restrict__ X,
                                               const float* __restrict__ W, int which) {
    __shared__ float Xs[32][33], Ws[32][33];
    const int n0 = blockIdx.y * 32, j0 = blockIdx.x * 32;
    const int tx = threadIdx.x, ty = threadIdx.y;
    float acc = 0.f;
    for (int k0 = 0; k0 < DM; k0 += 32) {
        Xs[ty][tx] = X[(size_t)(n0 + ty) * DM + k0 + tx];
        Ws[ty][tx] = W[(size_t)(j0 + ty) * DM + k0 + tx];
        __syncthreads();
#pragma unroll
        for (int kk = 0; kk < 32; kk++) acc += Xs[ty][kk] * Ws[tx][kk];
        __syncthreads();
    }
    const size_t o = (size_t)(n0 + ty) * DM + j0 + tx;
    if (which == 2) {
        g_Vp[o] = acc;
    } else {
        __half hi = __float2half(acc);
        __half lo = __float2half(acc - __half2float(hi));
        if (which == 0) { g_Qh[o] = hi; g_Ql[o] = lo; }
        else            { g_Kh[o] = hi; g_Kl[o] = lo; }
    }
}

// ---------------- kernel 3: P = relu(Q K^T) via HMMA, split precision ----------------
// CTA tile 128 (n, query) x 128 (m, key), k = 32 (one head dim). No pipeline needed.
#define QK_ROWB 80
#define QK_ARR (128 * QK_ROWB)   // 10240

__global__ void __launch_bounds__(256, 2) k_qk_mma() {
    __shared__ char qsm[4 * QK_ARR];   // Qh, Ql, Kh, Kl
    const uint32_t sb = smem_u32(qsm);
    const int tid = threadIdx.x;
    const int wid = tid >> 5, lane = tid & 31;
    const int h = blockIdx.z;
    const int m0 = blockIdx.x * 128;   // key tile
    const int n0 = blockIdx.y * 128;   // query tile

    // loads: per array 128 rows x 64B (32 halves); 4 chunks of 16B per row
    {
        const int r0 = tid >> 2, c = tid & 3;
#pragma unroll
        for (int j = 0; j < 2; j++) {
            const int r = r0 + j * 64;
            const uint32_t so = (uint32_t)(r * QK_ROWB + c * 16);
            const size_t qo = (size_t)(n0 + r) * DM + h * DH + c * 8;
            const size_t ko = (size_t)(m0 + r) * DM + h * DH + c * 8;
            cp16(sb + 0 * QK_ARR + so, g_Qh + qo);
            cp16(sb + 1 * QK_ARR + so, g_Ql + qo);
            cp16(sb + 2 * QK_ARR + so, g_Kh + ko);
            cp16(sb + 3 * QK_ARR + so, g_Kl + ko);
        }
    }
    asm volatile("cp.async.commit_group;" ::: "memory");
    asm volatile("cp.async.wait_group 0;" ::: "memory");
    __syncthreads();

    // warp layout: 2 (n) x 4 (m); warp tile 64 (n) x 32 (m)
    const int wm = wid & 1, wn = wid >> 1;
    float acc[4][4][4];
#pragma unroll
    for (int mi = 0; mi < 4; mi++)
#pragma unroll
        for (int ni = 0; ni < 4; ni++)
#pragma unroll
            for (int q = 0; q < 4; q++) acc[mi][ni][q] = 0.f;

    const int sel = lane >> 3, l7 = lane & 7;
    const int a_row = wm * 64 + (sel & 1) * 8 + l7;
    const int a_colb = (sel >> 1) * 16;
    const int b_row_base = wn * 32 + (sel >> 1) * 8 + l7;
    const int b_colb = (sel & 1) * 16;

#pragma unroll
    for (int ks = 0; ks < 2; ks++) {
        const int kb = ks * 32;
        uint32_t ahi[4][4], alo[4][4];
#pragma unroll
        for (int mi = 0; mi < 4; mi++) {
            const uint32_t ao = (uint32_t)((a_row + mi * 16) * QK_ROWB + kb + a_colb);
            ldsm_x4(ahi[mi], sb + 0 * QK_ARR + ao);
            ldsm_x4(alo[mi], sb + 1 * QK_ARR + ao);
        }
        uint32_t bhi[4][2], blo[4][2];
#pragma unroll
        for (int nb = 0; nb < 2; nb++) {
            const uint32_t bo = (uint32_t)((b_row_base + nb * 16) * QK_ROWB + kb + b_colb);
            uint32_t t[4];
            ldsm_x4(t, sb + 2 * QK_ARR + bo);
            bhi[2 * nb][0] = t[0]; bhi[2 * nb][1] = t[1];
            bhi[2 * nb + 1][0] = t[2]; bhi[2 * nb + 1][1] = t[3];
            ldsm_x4(t, sb + 3 * QK_ARR + bo);
            blo[2 * nb][0] = t[0]; blo[2 * nb][1] = t[1];
            blo[2 * nb + 1][0] = t[2]; blo[2 * nb + 1][1] = t[3];
        }
#pragma unroll
        for (int mi = 0; mi < 4; mi++)
#pragma unroll
            for (int ni = 0; ni < 4; ni++) mma16816(acc[mi][ni], ahi[mi], bhi[ni]);
#pragma unroll
        for (int mi = 0; mi < 4; mi++)
#pragma unroll
            for (int ni = 0; ni < 4; ni++) mma16816(acc[mi][ni], ahi[mi], blo[ni]);
#pragma unroll
        for (int mi = 0; mi < 4; mi++)
#pragma unroll
            for (int ni = 0; ni < 4; ni++) mma16816(acc[mi][ni], alo[mi], bhi[ni]);
    }

    // epilogue: relu + fp16 split
    const int er = lane >> 2, ec = (lane & 3) * 2;
#pragma unroll
    for (int mi = 0; mi < 4; mi++) {
#pragma unroll
        for (int ni = 0; ni < 4; ni++) {
            const int n = n0 + wm * 64 + mi * 16 + er;
            const int m = m0 + wn * 32 + ni * 8 + ec;
#pragma unroll
            for (int half = 0; half < 2; half++) {
                float p0 = fmaxf(acc[mi][ni][2 * half + 0], 0.f);
                float p1 = fmaxf(acc[mi][ni][2 * half + 1], 0.f);
                __half h0 = __float2half(p0), h1 = __float2half(p1);
                __half l0 = __float2half(p0 - __half2float(h0));
                __half l1 = __float2half(p1 - __half2float(h1));
                const size_t o = ((size_t)h * NN + n + half * 8) * NN + m;
                *(__half2*)(g_P_hi + o) = __halves2half2(h0, h1);
                *(__half2*)(g_P_lo + o) = __halves2half2(l0, l1);
            }
        }
    }
}

// ---------------- kernel 4: big GEMM (HMMA mma.sync, split precision) ----------------
// S[h][m][n] = (Phi·Rhi + Phi·Rlo + Plo·Rhi) / sqrt(32)
// CTA tile 128x128, K-chunk 32, 2-stage cp.async, 2 CTAs/SM, block-index swizzle.
#define ROWB 80
#define ARR_SZ (128 * ROWB)
#define STAGE_SZ (4 * ARR_SZ)            // Ahi, Alo, Bhi, Blo = 40960 B
#define GEMM_SMEM (2 * STAGE_SZ)         // 81920 B
#define KITERS (NN / 32)                 // 128

__global__ void __launch_bounds__(256, 2) k_gemm() {
    extern __shared__ char smem[];
    const uint32_t sb = smem_u32(smem);
    const int tid = threadIdx.x;
    const int wid = tid >> 5, lane = tid & 31;
    const int h = blockIdx.y;

    // swizzle: 8x8 CTA groups so concurrent CTAs share A and B tiles in L2
    const int bid = blockIdx.x;          // 0..1023
    const int g = bid >> 6;              // 0..15
    const int nx = ((g & 3) << 3) + (bid & 7);
    const int ny = ((g >> 2) << 3) + ((bid >> 3) & 7);
    const int m0 = ny * 128, n0 = nx * 128;

    const __half* __restrict__ Ahi = g_P_hi + ((size_t)h * NN + m0) * NN;
    const __half* __restrict__ Alo = g_P_lo + ((size_t)h * NN + m0) * NN;
    const __half* __restrict__ Bhi = g_RT_hi + (size_t)n0 * NN;
    const __half* __restrict__ Blo = g_RT_lo + (size_t)n0 * NN;

    const int r0l = tid >> 2, c0l = tid & 3;

    auto issue_stage = [&](int kc, int stage) {
        const uint32_t s0 = sb + stage * STAGE_SZ;
#pragma unroll
        for (int j = 0; j < 2; j++) {
            const int row = r0l + j * 64;
            const uint32_t so = (uint32_t)(row * ROWB + c0l * 16);
            const size_t go = (size_t)row * NN + kc + c0l * 8;
            cp16(s0 + 0 * ARR_SZ + so, Ahi + go);
            cp16(s0 + 1 * ARR_SZ + so, Alo + go);
            cp16(s0 + 2 * ARR_SZ + so, Bhi + go);
            cp16(s0 + 3 * ARR_SZ + so, Blo + go);
        }
        asm volatile("cp.async.commit_group;" ::: "memory");
    };

    // warp layout: 2 (M) x 4 (N); warp tile 64 (M) x 32 (N)
    const int wm = wid & 1, wn = wid >> 1;
    float acc[4][4][4];
#pragma unroll
    for (int mi = 0; mi < 4; mi++)
#pragma unroll
        for (int ni = 0; ni < 4; ni++)
#pragma unroll
            for (int q = 0; q < 4; q++) acc[mi][ni][q] = 0.f;

    const int sel = lane >> 3, l7 = lane & 7;
    const int a_row = wm * 64 + (sel & 1) * 8 + l7;
    const int a_colb = (sel >> 1) * 16;
    const int b_row_base = wn * 32 + (sel >> 1) * 8 + l7;
    const int b_colb = (sel & 1) * 16;

    issue_stage(0, 0);

    for (int it = 0; it < KITERS; it++) {
        __syncthreads();   // everyone done reading the buffer about to be overwritten
        if (it + 1 < KITERS) {
            issue_stage((it + 1) * 32, (it + 1) & 1);
            asm volatile("cp.async.wait_group 1;" ::: "memory");
        } else {
            asm volatile("cp.async.wait_group 0;" ::: "memory");
        }
        __syncthreads();

        const uint32_t s0 = sb + (it & 1) * STAGE_SZ;
        const uint32_t pAhi = s0 + 0 * ARR_SZ, pAlo = s0 + 1 * ARR_SZ;
        const uint32_t pBhi = s0 + 2 * ARR_SZ, pBlo = s0 + 3 * ARR_SZ;

#pragma unroll
        for (int ks = 0; ks < 2; ks++) {
            const int kb = ks * 32;
            uint32_t ahi[4][4], alo[4][4];
#pragma unroll
            for (int mi = 0; mi < 4; mi++) {
                const uint32_t ao = (uint32_t)((a_row + mi * 16) * ROWB + kb + a_colb);
                ldsm_x4(ahi[mi], pAhi + ao);
                ldsm_x4(alo[mi], pAlo + ao);
            }
            uint32_t bhi[4][2], blo[4][2];
#pragma unroll
            for (int nb = 0; nb < 2; nb++) {
                const uint32_t bo = (uint32_t)((b_row_base + nb * 16) * ROWB + kb + b_colb);
                uint32_t t[4];
                ldsm_x4(t, pBhi + bo);
                bhi[2 * nb][0] = t[0]; bhi[2 * nb][1] = t[1];
                bhi[2 * nb + 1][0] = t[2]; bhi[2 * nb + 1][1] = t[3];
                ldsm_x4(t, pBlo + bo);
                blo[2 * nb][0] = t[0]; blo[2 * nb][1] = t[1];
                blo[2 * nb + 1][0] = t[2]; blo[2 * nb + 1][1] = t[3];
            }
#pragma unroll
            for (int mi = 0; mi < 4; mi++)
#pragma unroll
                for (int ni = 0; ni < 4; ni++) mma16816(acc[mi][ni], ahi[mi], bhi[ni]);
#pragma unroll
            for (int mi = 0; mi < 4; mi++)
#pragma unroll
                for (int ni = 0; ni < 4; ni++) mma16816(acc[mi][ni], ahi[mi], blo[ni]);
#pragma unroll
            for (int mi = 0; mi < 4; mi++)
#pragma unroll
                for (int ni = 0; ni < 4; ni++) mma16816(acc[mi][ni], alo[mi], bhi[ni]);
        }
    }

    // epilogue
    const float inv_s = 0.17677669529663687f;  // 1/sqrt(32)
    const int er = lane >> 2, ec = (lane & 3) * 2;
#pragma unroll
    for (int mi = 0; mi < 4; mi++) {
#pragma unroll
        for (int ni = 0; ni < 4; ni++) {
            const int col = n0 + wn * 32 + ni * 8 + ec;
            const int row = m0 + wm * 64 + mi * 16 + er;
            float2 v0 = make_float2(acc[mi][ni][0] * inv_s, acc[mi][ni][1] * inv_s);
            float2 v1 = make_float2(acc[mi][ni][2] * inv_s, acc[mi][ni][3] * inv_s);
            *(float2*)(g_S + ((size_t)h * NN + row) * NN + col) = v0;
            *(float2*)(g_S + ((size_t)h * NN + row + 8) * NN + col) = v1;
        }
    }
}

// ---------------- kernel 5: softmax row-wise in place ----------------
__global__ void __launch_bounds__(256) k_softmax() {
    const size_t row = blockIdx.x;
    float* p = g_S + row * (size_t)NN;
    const int tid = threadIdx.x;
    float x[16];
    float mx = -1e30f;
#pragma unroll
    for (int i = 0; i < 16; i++) { x[i] = p[tid + (i << 8)]; mx = fmaxf(mx, x[i]); }
    __shared__ float red[8];
#pragma unroll
    for (int o = 16; o; o >>= 1) mx = fmaxf(mx, __shfl_xor_sync(0xffffffffu, mx, o));
    if ((tid & 31) == 0) red[tid >> 5] = mx;
    __syncthreads();
    mx = red[0];
#pragma unroll
    for (int i = 1; i < 8; i++) mx = fmaxf(mx, red[i]);
    float s = 0.f;
#pragma unroll
    for (int i = 0; i < 16; i++) { x[i] = __expf(x[i] - mx); s += x[i]; }
#pragma unroll
    for (int o = 16; o; o >>= 1) s += __shfl_xor_sync(0xffffffffu, s, o);
    __syncthreads();
    if ((tid & 31) == 0) red[tid >> 5] = s;
    __syncthreads();
    s = ((red[0] + red[1]) + (red[2] + red[3])) + ((red[4] + red[5]) + (red[6] + red[7]));
    const float inv = 1.0f / s;
#pragma unroll
    for (int i = 0; i < 16; i++) p[tid + (i << 8)] = x[i] * inv;
}

// ---------------- kernel 6: out[n][h*32+d] = sum_p attn[h][n][p] * V[p][h*32+d] ----------------
__global__ void __launch_bounds__(256) k_av(float* __restrict__ out) {
    const int h = blockIdx.y;
    const int n = blockIdx.x;
    const int tx = threadIdx.x;  // d: 0..31
    const int ty = threadIdx.y;  // p split: 0..7
    const float* __restrict__ arow = g_S + ((size_t)h * NN + n) * NN;
    const float* __restrict__ vptr = g_Vp + h * DH + tx;
    float a0 = 0.f, a1 = 0.f, a2 = 0.f, a3 = 0.f;
    for (int p = ty; p < NN; p += 32) {
        a0 += arow[p]      * vptr[(size_t)(p)      * DM];
        a1 += arow[p + 8]  * vptr[(size_t)(p + 8)  * DM];
        a2 += arow[p + 16] * vptr[(size_t)(p + 16) * DM];
        a3 += arow[p + 24] * vptr[(size_t)(p + 24) * DM];
    }
    float acc = (a0 + a1) + (a2 + a3);
    __shared__ float red[8][32];
    red[ty][tx] = acc;
    __syncthreads();
    if (ty == 0) {
        float s = ((red[0][tx] + red[1][tx]) + (red[2][tx] + red[3][tx])) +
                  ((red[4][tx] + red[5][tx]) + (red[6][tx] + red[7][tx]));
        out[(size_t)n * DM + h * DH + tx] = s;
    }
}

// ---------------- launch ----------------
extern "C" void kernel_launch(void* const* d_in, const int* in_sizes, int n_in,
                              void* d_out, int out_size) {
    (void)in_sizes; (void)n_in; (void)out_size;
    const float* Qin  = (const float*)d_in[0];
    const float* Kin  = (const float*)d_in[1];
    const float* Vin  = (const float*)d_in[2];
    // d_in[3] = adj_matrix: dead code in the reference
    const float* dist = (const float*)d_in[4];
    const float* WQ   = (const float*)d_in[5];
    const float* WK   = (const float*)d_in[6];
    const float* WV   = (const float*)d_in[7];
    float* out = (float*)d_out;

    k_rescale<<<dim3(128, 128), dim3(32, 32)>>>(dist);
    k_proj<<<dim3(8, 128), dim3(32, 32)>>>(Qin, WQ, 0);
    k_proj<<<dim3(8, 128), dim3(32, 32)>>>(Kin, WK, 1);
    k_proj<<<dim3(8, 128), dim3(32, 32)>>>(Vin, WV, 2);
    k_qk_mma<<<dim3(32, 32, 8), 256>>>();

    cudaFuncSetAttribute(k_gemm, cudaFuncAttributeMaxDynamicSharedMemorySize, GEMM_SMEM);
    k_gemm<<<dim3(1024, 8), 256, GEMM_SMEM>>>();

    k_softmax<<<dim3(NH * NN), 256>>>();
    k_av<<<dim3(NN, NH), dim3(32, 8)>>>(out);
}

// round 5
// speedup vs baseline: 1.4659x; 1.1762x over previous
#include <cuda_runtime.h>
#include <cuda_fp16.h>
#include <cstdint>
#include <cstddef>

#define NN 4096
#define DM 256
#define NH 8
#define DH 32

// ---------------- scratch (device globals; no allocation) ----------------
__device__ __half g_P_hi[(size_t)NH * NN * NN];   // relu(QK^T) hi split, [h][n][m]
__device__ __half g_P_lo[(size_t)NH * NN * NN];   // lo split
__device__ __half g_RT_hi[(size_t)NN * NN];       // rescale(dist)^T hi, [p][m]
__device__ __half g_RT_lo[(size_t)NN * NN];       // lo split
__device__ float  g_S[(size_t)NH * NN * NN];      // scores -> attn (in place)
__device__ __half g_Qh[(size_t)NN * DM];          // Q projection fp16 hi/lo
__device__ __half g_Ql[(size_t)NN * DM];
__device__ __half g_Kh[(size_t)NN * DM];
__device__ __half g_Kl[(size_t)NN * DM];
__device__ float  g_Vp[(size_t)NN * DM];

// ---------------- helpers ----------------
__device__ __forceinline__ uint32_t smem_u32(const void* p) {
    uint32_t a;
    asm("{ .reg .u64 t; cvta.to.shared.u64 t, %1; cvt.u32.u64 %0, t; }" : "=r"(a) : "l"(p));
    return a;
}

__device__ __forceinline__ void ldsm_x4(uint32_t* r, uint32_t addr) {
    asm volatile("ldmatrix.sync.aligned.m8n8.x4.shared.b16 {%0,%1,%2,%3}, [%4];"
                 : "=r"(r[0]), "=r"(r[1]), "=r"(r[2]), "=r"(r[3]) : "r"(addr));
}

__device__ __forceinline__ void mma16816(float* c, const uint32_t* a, const uint32_t* b) {
    asm volatile(
        "mma.sync.aligned.m16n8k16.row.col.f32.f16.f16.f32 "
        "{%0,%1,%2,%3}, {%4,%5,%6,%7}, {%8,%9}, {%0,%1,%2,%3};"
        : "+f"(c[0]), "+f"(c[1]), "+f"(c[2]), "+f"(c[3])
        : "r"(a[0]), "r"(a[1]), "r"(a[2]), "r"(a[3]), "r"(b[0]), "r"(b[1]));
}

__device__ __forceinline__ void cp16(uint32_t smem, const void* gmem) {
    asm volatile("cp.async.cg.shared.global [%0], [%1], 16;" :: "r"(smem), "l"(gmem));
}

// ---------------- kernel 1: R^T = rescale(dist)^T, fp16 split ----------------
__global__ void __launch_bounds__(1024) k_rescale(const float* __restrict__ dist) {
    __shared__ float t[32][33];
    const int m0 = blockIdx.y * 32, p0 = blockIdx.x * 32;
    const int tx = threadIdx.x, ty = threadIdx.y;
    float d = dist[(size_t)(m0 + ty) * NN + p0 + tx];
    t[ty][tx] = 3.718281828459045f / (1.0f + expf(1.0f - d));
    __syncthreads();
    float r = t[tx][ty];  // = R[m0+tx][p0+ty]
    __half hi = __float2half(r);
    float lo = r - __half2float(hi);
    size_t o = (size_t)(p0 + ty) * NN + m0 + tx;
    g_RT_hi[o] = hi;
    g_RT_lo[o] = __float2half(lo);
}

// ---------------- kernel 2: projections out[n][j] = sum_k X[n][k]*W[j][k] ----------------
// which: 0 -> Q (fp16 hi/lo), 1 -> K (fp16 hi/lo), 2 -> V (fp32)
__global__ void __launch_bounds__(1024) k_proj(const float* __restrict__ X,
                                               const float* __restrict__ W, int which) {
    __shared__ float Xs[32][33], Ws[32][33];
    const int n0 = blockIdx.y * 32, j0 = blockIdx.x * 32;
    const int tx = threadIdx.x, ty = threadIdx.y;
    float acc = 0.f;
    for (int k0 = 0; k0 < DM; k0 += 32) {
        Xs[ty][tx] = X[(size_t)(n0 + ty) * DM + k0 + tx];
        Ws[ty][tx] = W[(size_t)(j0 + ty) * DM + k0 + tx];
        __syncthreads();
#pragma unroll
        for (int kk = 0; kk < 32; kk++) acc += Xs[ty][kk] * Ws[tx][kk];
        __syncthreads();
    }
    const size_t o = (size_t)(n0 + ty) * DM + j0 + tx;
    if (which == 2) {
        g_Vp[o] = acc;
    } else {
        __half hi = __float2half(acc);
        __half lo = __float2half(acc - __half2float(hi));
        if (which == 0) { g_Qh[o] = hi; g_Ql[o] = lo; }
        else            { g_Kh[o] = hi; g_Kl[o] = lo; }
    }
}

// ---------------- kernel 3: P = relu(Q K^T) via HMMA, split precision ----------------
#define QK_ROWB 80
#define QK_ARR (128 * QK_ROWB)   // 10240

__global__ void __launch_bounds__(256, 2) k_qk_mma() {
    __shared__ char qsm[4 * QK_ARR];   // Qh, Ql, Kh, Kl
    const uint32_t sb = smem_u32(qsm);
    const int tid = threadIdx.x;
    const int wid = tid >> 5, lane = tid & 31;
    const int h = blockIdx.z;
    const int m0 = blockIdx.x * 128;   // key tile
    const int n0 = blockIdx.y * 128;   // query tile

    {
        const int r0 = tid >> 2, c = tid & 3;
#pragma unroll
        for (int j = 0; j < 2; j++) {
            const int r = r0 + j * 64;
            const uint32_t so = (uint32_t)(r * QK_ROWB + c * 16);
            const size_t qo = (size_t)(n0 + r) * DM + h * DH + c * 8;
            const size_t ko = (size_t)(m0 + r) * DM + h * DH + c * 8;
            cp16(sb + 0 * QK_ARR + so, g_Qh + qo);
            cp16(sb + 1 * QK_ARR + so, g_Ql + qo);
            cp16(sb + 2 * QK_ARR + so, g_Kh + ko);
            cp16(sb + 3 * QK_ARR + so, g_Kl + ko);
        }
    }
    asm volatile("cp.async.commit_group;" ::: "memory");
    asm volatile("cp.async.wait_group 0;" ::: "memory");
    __syncthreads();

    const int wm = wid & 1, wn = wid >> 1;
    float acc[4][4][4];
#pragma unroll
    for (int mi = 0; mi < 4; mi++)
#pragma unroll
        for (int ni = 0; ni < 4; ni++)
#pragma unroll
            for (int q = 0; q < 4; q++) acc[mi][ni][q] = 0.f;

    const int sel = lane >> 3, l7 = lane & 7;
    const int a_row = wm * 64 + (sel & 1) * 8 + l7;
    const int a_colb = (sel >> 1) * 16;
    const int b_row_base = wn * 32 + (sel >> 1) * 8 + l7;
    const int b_colb = (sel & 1) * 16;

#pragma unroll
    for (int ks = 0; ks < 2; ks++) {
        const int kb = ks * 32;
        uint32_t ahi[4][4], alo[4][4];
#pragma unroll
        for (int mi = 0; mi < 4; mi++) {
            const uint32_t ao = (uint32_t)((a_row + mi * 16) * QK_ROWB + kb + a_colb);
            ldsm_x4(ahi[mi], sb + 0 * QK_ARR + ao);
            ldsm_x4(alo[mi], sb + 1 * QK_ARR + ao);
        }
        uint32_t bhi[4][2], blo[4][2];
#pragma unroll
        for (int nb = 0; nb < 2; nb++) {
            const uint32_t bo = (uint32_t)((b_row_base + nb * 16) * QK_ROWB + kb + b_colb);
            uint32_t t[4];
            ldsm_x4(t, sb + 2 * QK_ARR + bo);
            bhi[2 * nb][0] = t[0]; bhi[2 * nb][1] = t[1];
            bhi[2 * nb + 1][0] = t[2]; bhi[2 * nb + 1][1] = t[3];
            ldsm_x4(t, sb + 3 * QK_ARR + bo);
            blo[2 * nb][0] = t[0]; blo[2 * nb][1] = t[1];
            blo[2 * nb + 1][0] = t[2]; blo[2 * nb + 1][1] = t[3];
        }
#pragma unroll
        for (int mi = 0; mi < 4; mi++)
#pragma unroll
            for (int ni = 0; ni < 4; ni++) mma16816(acc[mi][ni], ahi[mi], bhi[ni]);
#pragma unroll
        for (int mi = 0; mi < 4; mi++)
#pragma unroll
            for (int ni = 0; ni < 4; ni++) mma16816(acc[mi][ni], ahi[mi], blo[ni]);
#pragma unroll
        for (int mi = 0; mi < 4; mi++)
#pragma unroll
            for (int ni = 0; ni < 4; ni++) mma16816(acc[mi][ni], alo[mi], bhi[ni]);
    }

    const int er = lane >> 2, ec = (lane & 3) * 2;
#pragma unroll
    for (int mi = 0; mi < 4; mi++) {
#pragma unroll
        for (int ni = 0; ni < 4; ni++) {
            const int n = n0 + wm * 64 + mi * 16 + er;
            const int m = m0 + wn * 32 + ni * 8 + ec;
#pragma unroll
            for (int half = 0; half < 2; half++) {
                float p0 = fmaxf(acc[mi][ni][2 * half + 0], 0.f);
                float p1 = fmaxf(acc[mi][ni][2 * half + 1], 0.f);
                __half h0 = __float2half(p0), h1 = __float2half(p1);
                __half l0 = __float2half(p0 - __half2float(h0));
                __half l1 = __float2half(p1 - __half2float(h1));
                const size_t o = ((size_t)h * NN + n + half * 8) * NN + m;
                *(__half2*)(g_P_hi + o) = __halves2half2(h0, h1);
                *(__half2*)(g_P_lo + o) = __halves2half2(l0, l1);
            }
        }
    }
}

// ---------------- kernel 4: big GEMM (HMMA, split precision) ----------------
// CTA tile 256(M) x 128(N), K-chunk 32, 3-stage cp.async, 512 threads, 1 CTA/SM.
#define ROWB 80
#define A_ARR (256 * ROWB)               // 20480
#define B_ARR (128 * ROWB)               // 10240
#define STAGE_SZ (2 * A_ARR + 2 * B_ARR) // 61440
#define GEMM_SMEM (3 * STAGE_SZ)         // 184320
#define KITERS (NN / 32)                 // 128

__global__ void __launch_bounds__(512, 1) k_gemm() {
    extern __shared__ char smem[];
    const uint32_t sb = smem_u32(smem);
    const int tid = threadIdx.x;
    const int wid = tid >> 5, lane = tid & 31;
    const int h = blockIdx.y;

    // swizzle: groups of 8(m) x 16(n) CTAs -> 64MB working set, fits L2
    const int bid = blockIdx.x;          // 0..511
    const int g = bid >> 7;              // 0..3
    const int gx = g & 1, gy = g >> 1;
    const int ny = gy * 8 + (bid & 7);          // 0..15 (m-tile, 256 rows)
    const int nx = gx * 16 + ((bid >> 3) & 15); // 0..31 (n-tile, 128 cols)
    const int m0 = ny * 256, n0 = nx * 128;

    const __half* __restrict__ Ahi = g_P_hi + ((size_t)h * NN + m0) * NN;
    const __half* __restrict__ Alo = g_P_lo + ((size_t)h * NN + m0) * NN;
    const __half* __restrict__ Bhi = g_RT_hi + (size_t)n0 * NN;
    const __half* __restrict__ Blo = g_RT_lo + (size_t)n0 * NN;

    auto issue_stage = [&](int it) {
        if (it < KITERS) {
            const uint32_t s0 = sb + (it % 3) * STAGE_SZ;
            const int kc = it * 32;
#pragma unroll
            for (int i = 0; i < 4; i++) {      // A: 2048 cp16 over 512 thr
                const int idx = i * 512 + tid;
                const int arr = idx >> 10, rem = idx & 1023;
                const int r = rem >> 2, c = rem & 3;
                const __half* src = (arr ? Alo : Ahi) + (size_t)r * NN + kc + c * 8;
                cp16(s0 + arr * A_ARR + (uint32_t)(r * ROWB + c * 16), src);
            }
#pragma unroll
            for (int i = 0; i < 2; i++) {      // B: 1024 cp16
                const int idx = i * 512 + tid;
                const int arr = idx >> 9, rem = idx & 511;
                const int r = rem >> 2, c = rem & 3;
                const __half* src = (arr ? Blo : Bhi) + (size_t)r * NN + kc + c * 8;
                cp16(s0 + 2 * A_ARR + arr * B_ARR + (uint32_t)(r * ROWB + c * 16), src);
            }
        }
        asm volatile("cp.async.commit_group;" ::: "memory");
    };

    // warp layout: 4 (M) x 4 (N); warp tile 64 (M) x 32 (N)
    const int wm = wid & 3, wn = wid >> 2;
    float acc[4][4][4];
#pragma unroll
    for (int mi = 0; mi < 4; mi++)
#pragma unroll
        for (int ni = 0; ni < 4; ni++)
#pragma unroll
            for (int q = 0; q < 4; q++) acc[mi][ni][q] = 0.f;

    const int sel = lane >> 3, l7 = lane & 7;
    const int a_row = wm * 64 + (sel & 1) * 8 + l7;
    const int a_colb = (sel >> 1) * 16;
    const int b_row_base = wn * 32 + (sel >> 1) * 8 + l7;
    const int b_colb = (sel & 1) * 16;

    issue_stage(0);
    issue_stage(1);

    for (int it = 0; it < KITERS; it++) {
        asm volatile("cp.async.wait_group 1;" ::: "memory");
        __syncthreads();
        issue_stage(it + 2);

        const uint32_t s0 = sb + (it % 3) * STAGE_SZ;
        const uint32_t pAhi = s0, pAlo = s0 + A_ARR;
        const uint32_t pBhi = s0 + 2 * A_ARR, pBlo = pBhi + B_ARR;

#pragma unroll
        for (int ks = 0; ks < 2; ks++) {
            const int kb = ks * 32;
            uint32_t ahi[4][4], alo[4][4];
#pragma unroll
            for (int mi = 0; mi < 4; mi++) {
                const uint32_t ao = (uint32_t)((a_row + mi * 16) * ROWB + kb + a_colb);
                ldsm_x4(ahi[mi], pAhi + ao);
                ldsm_x4(alo[mi], pAlo + ao);
            }
            uint32_t bhi[4][2], blo[4][2];
#pragma unroll
            for (int nb = 0; nb < 2; nb++) {
                const uint32_t bo = (uint32_t)((b_row_base + nb * 16) * ROWB + kb + b_colb);
                uint32_t t[4];
                ldsm_x4(t, pBhi + bo);
                bhi[2 * nb][0] = t[0]; bhi[2 * nb][1] = t[1];
                bhi[2 * nb + 1][0] = t[2]; bhi[2 * nb + 1][1] = t[3];
                ldsm_x4(t, pBlo + bo);
                blo[2 * nb][0] = t[0]; blo[2 * nb][1] = t[1];
                blo[2 * nb + 1][0] = t[2]; blo[2 * nb + 1][1] = t[3];
            }
#pragma unroll
            for (int mi = 0; mi < 4; mi++)
#pragma unroll
                for (int ni = 0; ni < 4; ni++) mma16816(acc[mi][ni], ahi[mi], bhi[ni]);
#pragma unroll
            for (int mi = 0; mi < 4; mi++)
#pragma unroll
                for (int ni = 0; ni < 4; ni++) mma16816(acc[mi][ni], ahi[mi], blo[ni]);
#pragma unroll
            for (int mi = 0; mi < 4; mi++)
#pragma unroll
                for (int ni = 0; ni < 4; ni++) mma16816(acc[mi][ni], alo[mi], bhi[ni]);
        }
    }

    // epilogue
    const float inv_s = 0.17677669529663687f;  // 1/sqrt(32)
    const int er = lane >> 2, ec = (lane & 3) * 2;
#pragma unroll
    for (int mi = 0; mi < 4; mi++) {
#pragma unroll
        for (int ni = 0; ni < 4; ni++) {
            const int col = n0 + wn * 32 + ni * 8 + ec;
            const int row = m0 + wm * 64 + mi * 16 + er;
            float2 v0 = make_float2(acc[mi][ni][0] * inv_s, acc[mi][ni][1] * inv_s);
            float2 v1 = make_float2(acc[mi][ni][2] * inv_s, acc[mi][ni][3] * inv_s);
            *(float2*)(g_S + ((size_t)h * NN + row) * NN + col) = v0;
            *(float2*)(g_S + ((size_t)h * NN + row + 8) * NN + col) = v1;
        }
    }
}

// ---------------- kernel 5: softmax row-wise in place ----------------
__global__ void __launch_bounds__(256) k_softmax() {
    const size_t row = blockIdx.x;
    float* p = g_S + row * (size_t)NN;
    const int tid = threadIdx.x;
    float x[16];
    float mx = -1e30f;
#pragma unroll
    for (int i = 0; i < 16; i++) { x[i] = p[tid + (i << 8)]; mx = fmaxf(mx, x[i]); }
    __shared__ float red[8];
#pragma unroll
    for (int o = 16; o; o >>= 1) mx = fmaxf(mx, __shfl_xor_sync(0xffffffffu, mx, o));
    if ((tid & 31) == 0) red[tid >> 5] = mx;
    __syncthreads();
    mx = red[0];
#pragma unroll
    for (int i = 1; i < 8; i++) mx = fmaxf(mx, red[i]);
    float s = 0.f;
#pragma unroll
    for (int i = 0; i < 16; i++) { x[i] = __expf(x[i] - mx); s += x[i]; }
#pragma unroll
    for (int o = 16; o; o >>= 1) s += __shfl_xor_sync(0xffffffffu, s, o);
    __syncthreads();
    if ((tid & 31) == 0) red[tid >> 5] = s;
    __syncthreads();
    s = ((red[0] + red[1]) + (red[2] + red[3])) + ((red[4] + red[5]) + (red[6] + red[7]));
    const float inv = 1.0f / s;
#pragma unroll
    for (int i = 0; i < 16; i++) p[tid + (i << 8)] = x[i] * inv;
}

// ---------------- kernel 6: out = attn @ V, smem-tiled ----------------
// grid (64, 8): 64-row block of attn rows, head. Block 256 threads.
__global__ void __launch_bounds__(256) k_av(float* __restrict__ out) {
    __shared__ float As[64][128];
    __shared__ float Vs[128][32];
    const int h = blockIdx.y, n0 = blockIdx.x * 64;
    const int tid = threadIdx.x;
    const int d = tid & 31, ng = tid >> 5;
    float acc[8];
#pragma unroll
    for (int j = 0; j < 8; j++) acc[j] = 0.f;

    for (int p0 = 0; p0 < NN; p0 += 128) {
        __syncthreads();
#pragma unroll
        for (int i = 0; i < 8; i++) {   // attn tile 64x128
            const int idx = tid + i * 256;
            const int r = idx >> 5, c4 = (idx & 31) * 4;
            *(float4*)&As[r][c4] = *(const float4*)(g_S + ((size_t)h * NN + n0 + r) * NN + p0 + c4);
        }
#pragma unroll
        for (int i = 0; i < 4; i++) {   // V tile 128x32
            const int idx = tid + i * 256;
            const int r = idx >> 3, c4 = (idx & 7) * 4;
            *(float4*)&Vs[r][c4] = *(const float4*)(g_Vp + (size_t)(p0 + r) * DM + h * DH + c4);
        }
        __syncthreads();
#pragma unroll 4
        for (int p = 0; p < 128; p++) {
            const float v = Vs[p][d];
#pragma unroll
            for (int j = 0; j < 8; j++) acc[j] += As[ng + 8 * j][p] * v;
        }
    }
#pragma unroll
    for (int j = 0; j < 8; j++)
        out[(size_t)(n0 + ng + 8 * j) * DM + h * DH + d] = acc[j];
}

// ---------------- launch ----------------
extern "C" void kernel_launch(void* const* d_in, const int* in_sizes, int n_in,
                              void* d_out, int out_size) {
    (void)in_sizes; (void)n_in; (void)out_size;
    const float* Qin  = (const float*)d_in[0];
    const float* Kin  = (const float*)d_in[1];
    const float* Vin  = (const float*)d_in[2];
    // d_in[3] = adj_matrix: dead code in the reference
    const float* dist = (const float*)d_in[4];
    const float* WQ   = (const float*)d_in[5];
    const float* WK   = (const float*)d_in[6];
    const float* WV   = (const float*)d_in[7];
    float* out = (float*)d_out;

    k_rescale<<<dim3(128, 128), dim3(32, 32)>>>(dist);
    k_proj<<<dim3(8, 128), dim3(32, 32)>>>(Qin, WQ, 0);
    k_proj<<<dim3(8, 128), dim3(32, 32)>>>(Kin, WK, 1);
    k_proj<<<dim3(8, 128), dim3(32, 32)>>>(Vin, WV, 2);
    k_qk_mma<<<dim3(32, 32, 8), 256>>>();

    cudaFuncSetAttribute(k_gemm, cudaFuncAttributeMaxDynamicSharedMemorySize, GEMM_SMEM);
    k_gemm<<<dim3(512, 8), 512, GEMM_SMEM>>>();

    k_softmax<<<dim3(NH * NN), 256>>>();
    k_av<<<dim3(64, 8), 256>>>(out);
}